// round 1
// baseline (speedup 1.0000x reference)
#include <cuda_runtime.h>
#include <cuda_bf16.h>
#include <cstdint>

// PFNLayer pillar feature decoration.
//   pillars:  (P, 32, 4) f32
//   coors:    (P, 4)     i32
//   npoints:  (P,)       i32
// features (P, 9, 32):
//   ch0 = x - (coors[:,1]*0.16 + 0.08)
//   ch1 = y - (coors[:,2]*0.16 + 0.08)   // upstream bug: uses x_offset, replicated
//   ch2 = z, ch3 = w
//   ch4..6 = xyz - mean_xyz   (mean = sum over ALL 32 slots / true count n)
//   ch7 = ch0, ch8 = ch1
//   all channels zeroed for slot j >= n
// Output buffer: [coors cast to f32 (P*4)] ++ [features (P*9*32)] — coors part
// emitted only if out_size indicates it.

static constexpr long long P_TOTAL = 200000;
static constexpr int MAX_PTS = 32;
static constexpr float VOXEL = 0.16f;
static constexpr float OFFSET = 0.08f;   // voxel/2 + 0.0, used for BOTH x and y (ref bug)

__global__ void __launch_bounds__(256)
pfn_feature_kernel(const float4* __restrict__ pillars,   // (P*32) float4
                   const int4*   __restrict__ coors,     // (P) int4
                   const int*    __restrict__ npts,      // (P)
                   float*        __restrict__ out_feat,  // (P*9*32)
                   int P)
{
    const int warp_in_block = threadIdx.x >> 5;
    const int lane = threadIdx.x & 31;
    const int p = blockIdx.x * 8 + warp_in_block;
    if (p >= P) return;

    // one float4 per lane — 512B coalesced per warp
    const float4 v = pillars[(long long)p * MAX_PTS + lane];

    // warp reduction: sum x,y,z over all 32 slots (padding included, per reference)
    float sx = v.x, sy = v.y, sz = v.z;
    #pragma unroll
    for (int ofs = 16; ofs > 0; ofs >>= 1) {
        sx += __shfl_xor_sync(0xFFFFFFFFu, sx, ofs);
        sy += __shfl_xor_sync(0xFFFFFFFFu, sy, ofs);
        sz += __shfl_xor_sync(0xFFFFFFFFu, sz, ofs);
    }

    const int   n    = npts[p];
    const float invn = 1.0f / (float)n;
    const float mx = sx * invn, my = sy * invn, mz = sz * invn;

    const int4 c = coors[p];
    const float cx = (float)c.y * VOXEL + OFFSET;
    const float cy = (float)c.z * VOXEL + OFFSET;  // ref bug: x_offset for y too

    const float m = (lane < n) ? 1.0f : 0.0f;

    const float off_x = (v.x - cx) * m;
    const float off_y = (v.y - cy) * m;

    float* o = out_feat + (long long)p * (9 * MAX_PTS) + lane;
    o[0 * 32] = off_x;
    o[1 * 32] = off_y;
    o[2 * 32] = v.z * m;
    o[3 * 32] = v.w * m;
    o[4 * 32] = (v.x - mx) * m;
    o[5 * 32] = (v.y - my) * m;
    o[6 * 32] = (v.z - mz) * m;
    o[7 * 32] = off_x;
    o[8 * 32] = off_y;
}

__global__ void __launch_bounds__(256)
coors_copy_kernel(const int* __restrict__ coors, float* __restrict__ out, int n)
{
    int i = blockIdx.x * 256 + threadIdx.x;
    if (i < n) out[i] = (float)coors[i];
}

extern "C" void kernel_launch(void* const* d_in, const int* in_sizes, int n_in,
                              void* d_out, int out_size)
{
    const float* pillars = (const float*)d_in[0];
    const int*   coors   = (const int*)d_in[1];
    const int*   npts    = (const int*)d_in[2];
    float* out = (float*)d_out;

    const long long P = (long long)in_sizes[2];          // npoints count = P
    const long long coors_elems = P * 4;
    const long long feat_elems  = P * 9 * MAX_PTS;

    float* out_feat = out;
    if ((long long)out_size >= coors_elems + feat_elems) {
        // tuple output: coors (as f32) first, then features
        int nblocks = (int)((coors_elems + 255) / 256);
        coors_copy_kernel<<<nblocks, 256>>>(coors, out, (int)coors_elems);
        out_feat = out + coors_elems;
    }

    const int blocks = (int)((P + 7) / 8);               // 8 pillars (warps) per block
    pfn_feature_kernel<<<blocks, 256>>>(
        (const float4*)pillars, (const int4*)coors, npts, out_feat, (int)P);
}

// round 2
// speedup vs baseline: 1.1191x; 1.1191x over previous
#include <cuda_runtime.h>
#include <cuda_bf16.h>
#include <cstdint>

// PFNLayer pillar feature decoration — fused single kernel.
//   pillars:  (P, 32, 4) f32
//   coors:    (P, 4)     i32
//   npoints:  (P,)       i32
// Output buffer: [coors cast to f32 (P*4)] ++ [features (P,9,32) f32]
// features:
//   ch0 = x - (coors[:,1]*0.16 + 0.08)
//   ch1 = y - (coors[:,2]*0.16 + 0.08)   // upstream bug: x_offset for y, replicated
//   ch2 = z, ch3 = w
//   ch4..6 = xyz - mean_xyz   (mean = sum over ALL 32 slots / true count n)
//   ch7 = ch0, ch8 = ch1
//   channels zeroed for slot j >= n

static constexpr int MAX_PTS = 32;
static constexpr float VOXEL = 0.16f;
static constexpr float OFFSET = 0.08f;   // voxel/2 + 0.0, used for BOTH x and y (ref bug)

__global__ void __launch_bounds__(256)
pfn_fused_kernel(const float4* __restrict__ pillars,   // (P*32) float4
                 const int4*   __restrict__ coors,     // (P) int4
                 const int*    __restrict__ npts,      // (P)
                 float*        __restrict__ out_coors, // (P*4) or nullptr
                 float*        __restrict__ out_feat,  // (P*9*32)
                 int P)
{
    const int warp_in_block = threadIdx.x >> 5;
    const int lane = threadIdx.x & 31;
    const int p = blockIdx.x * 8 + warp_in_block;
    if (p >= P) return;

    // one float4 per lane — 512B coalesced per warp; streaming (no L2 reuse)
    const float4 v = __ldcs(&pillars[(long long)p * MAX_PTS + lane]);

    // warp reduction: sum x,y,z over ALL 32 slots (padding included, per reference)
    float sx = v.x, sy = v.y, sz = v.z;
    #pragma unroll
    for (int ofs = 16; ofs > 0; ofs >>= 1) {
        sx += __shfl_xor_sync(0xFFFFFFFFu, sx, ofs);
        sy += __shfl_xor_sync(0xFFFFFFFFu, sy, ofs);
        sz += __shfl_xor_sync(0xFFFFFFFFu, sz, ofs);
    }

    const int   n    = __ldg(&npts[p]);
    const float invn = 1.0f / (float)n;
    const float mx = sx * invn, my = sy * invn, mz = sz * invn;

    const int4 c = __ldg(&coors[p]);

    // fused coors -> float copy (tuple output); lane 0 writes 16B, warps in a
    // block cover a contiguous 128B span of the coors region
    if (out_coors != nullptr && lane == 0) {
        float4 cf = make_float4((float)c.x, (float)c.y, (float)c.z, (float)c.w);
        __stcs(reinterpret_cast<float4*>(out_coors) + p, cf);
    }

    const float cx = (float)c.y * VOXEL + OFFSET;
    const float cy = (float)c.z * VOXEL + OFFSET;  // ref bug: x_offset for y too

    const float m = (lane < n) ? 1.0f : 0.0f;

    const float off_x = (v.x - cx) * m;
    const float off_y = (v.y - cy) * m;

    float* o = out_feat + (long long)p * (9 * MAX_PTS) + lane;
    __stcs(&o[0 * 32], off_x);
    __stcs(&o[1 * 32], off_y);
    __stcs(&o[2 * 32], v.z * m);
    __stcs(&o[3 * 32], v.w * m);
    __stcs(&o[4 * 32], (v.x - mx) * m);
    __stcs(&o[5 * 32], (v.y - my) * m);
    __stcs(&o[6 * 32], (v.z - mz) * m);
    __stcs(&o[7 * 32], off_x);
    __stcs(&o[8 * 32], off_y);
}

extern "C" void kernel_launch(void* const* d_in, const int* in_sizes, int n_in,
                              void* d_out, int out_size)
{
    const float* pillars = (const float*)d_in[0];
    const int*   coors   = (const int*)d_in[1];
    const int*   npts    = (const int*)d_in[2];
    float* out = (float*)d_out;

    const long long P = (long long)in_sizes[2];          // npoints count = P
    const long long coors_elems = P * 4;
    const long long feat_elems  = P * 9 * MAX_PTS;

    float* out_coors = nullptr;
    float* out_feat  = out;
    if ((long long)out_size >= coors_elems + feat_elems) {
        out_coors = out;
        out_feat  = out + coors_elems;
    }

    const int blocks = (int)((P + 7) / 8);               // 8 pillars (warps) per block
    pfn_fused_kernel<<<blocks, 256>>>(
        (const float4*)pillars, (const int4*)coors, npts, out_coors, out_feat, (int)P);
}